// round 13
// baseline (speedup 1.0000x reference)
#include <cuda_runtime.h>
#include <cuda_bf16.h>
#include <math.h>
#include <stdint.h>

// Problem constants
#define L_SEQ  2048
#define DMODEL 1024
#define DI     2048
#define NB     4
#define DSTATE 16
#define DTRANK 64
#define MTOT   (NB * L_SEQ)   // 8192

// ---------------------------------------------------------------------------
// Scratch (device globals)
// ---------------------------------------------------------------------------
__device__ float g_xz   [(size_t)MTOT * 4096];
__device__ float g_uact [(size_t)MTOT * DI];
__device__ float g_xdbl [(size_t)MTOT * 96];
__device__ float g_delta[(size_t)MTOT * DI];
__device__ float g_xpart[4][(size_t)MTOT * 96];   // x_proj split-K partials

__device__ __nv_bfloat16 g_xT_hi [(size_t)MTOT * DMODEL];
__device__ __nv_bfloat16 g_xT_lo [(size_t)MTOT * DMODEL];
__device__ __nv_bfloat16 g_ua_hi [(size_t)MTOT * DI];
__device__ __nv_bfloat16 g_ua_lo [(size_t)MTOT * DI];
__device__ __nv_bfloat16 g_xd_hi [(size_t)MTOT * 96];
__device__ __nv_bfloat16 g_xd_lo [(size_t)MTOT * 96];
__device__ __nv_bfloat16 g_y_hi  [(size_t)MTOT * DI];
__device__ __nv_bfloat16 g_y_lo  [(size_t)MTOT * DI];
__device__ __nv_bfloat16 g_t1_hi [(size_t)MTOT * DMODEL];
__device__ __nv_bfloat16 g_t1_lo [(size_t)MTOT * DMODEL];
__device__ __nv_bfloat16 g_inw_hi[(size_t)4096 * DMODEL];
__device__ __nv_bfloat16 g_inw_lo[(size_t)4096 * DMODEL];
__device__ __nv_bfloat16 g_xpw_hi[(size_t)96 * DI];
__device__ __nv_bfloat16 g_xpw_lo[(size_t)96 * DI];
__device__ __nv_bfloat16 g_dtw_hi[(size_t)DI * DTRANK];
__device__ __nv_bfloat16 g_dtw_lo[(size_t)DI * DTRANK];
__device__ __nv_bfloat16 g_ow_hi [(size_t)DMODEL * DI];
__device__ __nv_bfloat16 g_ow_lo [(size_t)DMODEL * DI];
__device__ __nv_bfloat16 g_pw_hi [(size_t)DMODEL * DMODEL];
__device__ __nv_bfloat16 g_pw_lo [(size_t)DMODEL * DMODEL];

// ---------------------------------------------------------------------------
// mma.sync helpers (plain sm_80+ PTX)
// ---------------------------------------------------------------------------
__device__ __forceinline__ uint32_t smem_u32_of(const void* p) {
    uint32_t a;
    asm("{ .reg .u64 t; cvta.to.shared.u64 t, %1; cvt.u32.u64 %0, t; }"
        : "=r"(a) : "l"(p));
    return a;
}
__device__ __forceinline__ void ldm_x4(uint32_t* r, uint32_t addr) {
    asm volatile("ldmatrix.sync.aligned.m8n8.x4.shared.b16 {%0,%1,%2,%3}, [%4];"
                 : "=r"(r[0]), "=r"(r[1]), "=r"(r[2]), "=r"(r[3]) : "r"(addr));
}
__device__ __forceinline__ void ldm_x2(uint32_t* r, uint32_t addr) {
    asm volatile("ldmatrix.sync.aligned.m8n8.x2.shared.b16 {%0,%1}, [%2];"
                 : "=r"(r[0]), "=r"(r[1]) : "r"(addr));
}
__device__ __forceinline__ void mma16816(float* c, const uint32_t* a, const uint32_t* b) {
    asm volatile(
        "mma.sync.aligned.m16n8k16.row.col.f32.bf16.bf16.f32 "
        "{%0,%1,%2,%3}, {%4,%5,%6,%7}, {%8,%9}, {%0,%1,%2,%3};"
        : "+f"(c[0]), "+f"(c[1]), "+f"(c[2]), "+f"(c[3])
        : "r"(a[0]), "r"(a[1]), "r"(a[2]), "r"(a[3]), "r"(b[0]), "r"(b[1]));
}
__device__ __forceinline__ void cpa16(uint32_t dst, const void* src, int szbytes) {
    asm volatile("cp.async.cg.shared.global [%0], [%1], 16, %2;"
                 :: "r"(dst), "l"(src), "r"(szbytes));
}

#define TPITCH   80
#define TILE_B   10240
#define BUF_B    40960
#define SMEM_PIPE (3 * BUF_B)    // 3-stage pipeline = 122880 B

// ---------------------------------------------------------------------------
// Tensor-core GEMM (bf16 2-term split, 3 MMAs, term-major scheduling).
// CTA 128x128, BK=32, 256 threads (8 warps of 64x32).
// 3-stage cp.async pipeline, issue-ahead-2, ONE barrier per chunk.
// Split-K aware: blockIdx.z selects K-slice of length ksl.
// EPI 0: fp32   EPI 2: softplus(v+bias) fp32   EPI 3: bf16-split only
// EPI 4: (v+bias) transposed store
// ---------------------------------------------------------------------------
template <int EPI>
__global__ void __launch_bounds__(256)
tgemm_kernel(const __nv_bfloat16* __restrict__ Ahi, const __nv_bfloat16* __restrict__ Alo, int lda,
             const __nv_bfloat16* __restrict__ Bhi, const __nv_bfloat16* __restrict__ Blo, int ldb,
             int ksl, int Nreal, size_t pstride,
             float* __restrict__ Cf, int ldc, const float* __restrict__ bias,
             __nv_bfloat16* __restrict__ Ohi, __nv_bfloat16* __restrict__ Olo, int ldo)
{
    extern __shared__ __align__(128) char smem[];
    const int tid  = threadIdx.x;
    const int lane = tid & 31;
    const int wm   = (tid >> 5) & 1;
    const int wn   = tid >> 6;
    const int n0   = blockIdx.x * 128;
    const int m0   = blockIdx.y * 128;
    const int kbase = blockIdx.z * ksl;
    const uint32_t sb = smem_u32_of(smem);

    float acc[4][4][4];
#pragma unroll
    for (int i = 0; i < 4; i++)
#pragma unroll
        for (int j = 0; j < 4; j++)
#pragma unroll
            for (int q = 0; q < 4; q++) acc[i][j][q] = 0.f;

    const int r0  = (tid * 2) >> 2;
    const int s0  = (tid * 2) & 3;
    const int r1  = (tid * 2 + 1) >> 2;
    const int s1  = (tid * 2 + 1) & 3;

    auto issue = [&](int buf, int c) {
        const int k0 = kbase + (c << 5);
        const uint32_t base = sb + buf * BUF_B;
        {
            const uint32_t d = base + r0 * TPITCH + s0 * 16;
            cpa16(d,            Ahi + (size_t)(m0 + r0) * lda + k0 + s0 * 8, 16);
            cpa16(d + TILE_B,   Alo + (size_t)(m0 + r0) * lda + k0 + s0 * 8, 16);
            const bool ok = (n0 + r0) < Nreal;
            const int  nr = ok ? (n0 + r0) : 0;
            cpa16(d + 2 * TILE_B, Bhi + (size_t)nr * ldb + k0 + s0 * 8, ok ? 16 : 0);
            cpa16(d + 3 * TILE_B, Blo + (size_t)nr * ldb + k0 + s0 * 8, ok ? 16 : 0);
        }
        {
            const uint32_t d = base + r1 * TPITCH + s1 * 16;
            cpa16(d,            Ahi + (size_t)(m0 + r1) * lda + k0 + s1 * 8, 16);
            cpa16(d + TILE_B,   Alo + (size_t)(m0 + r1) * lda + k0 + s1 * 8, 16);
            const bool ok = (n0 + r1) < Nreal;
            const int  nr = ok ? (n0 + r1) : 0;
            cpa16(d + 2 * TILE_B, Bhi + (size_t)nr * ldb + k0 + s1 * 8, ok ? 16 : 0);
            cpa16(d + 3 * TILE_B, Blo + (size_t)nr * ldb + k0 + s1 * 8, ok ? 16 : 0);
        }
        asm volatile("cp.async.commit_group;");
    };

    const uint32_t aoff =
        (uint32_t)((wm * 64 + (lane & 7) + 8 * ((lane >> 3) & 1)) * TPITCH + (8 * (lane >> 4)) * 2);
    const uint32_t boff =
        (uint32_t)((wn * 32 + (lane & 7)) * TPITCH + (8 * ((lane >> 3) & 1)) * 2);

    const int nchunks = ksl >> 5;
    issue(0, 0);
    if (nchunks > 1) issue(1, 1);

    int buf = 0;
    for (int c = 0; c < nchunks; c++) {
        if (c + 1 < nchunks) {
            asm volatile("cp.async.wait_group 1;");
        } else {
            asm volatile("cp.async.wait_group 0;");
        }
        __syncthreads();
        if (c + 2 < nchunks) {
            int nb = buf + 2;
            if (nb >= 3) nb -= 3;
            issue(nb, c + 2);
        }

        const uint32_t base = sb + buf * BUF_B;
#pragma unroll
        for (int ks = 0; ks < 2; ks++) {
            const uint32_t kb = ks * 32;
            // ---- load ALL fragments for this k-step first ----
            uint32_t bh[4][2], bl[4][2], ah[4][4], al[4][4];
#pragma unroll
            for (int j = 0; j < 4; j++) {
                ldm_x2(bh[j], base + 2 * TILE_B + boff + j * (8 * TPITCH) + kb);
                ldm_x2(bl[j], base + 3 * TILE_B + boff + j * (8 * TPITCH) + kb);
            }
#pragma unroll
            for (int i = 0; i < 4; i++) {
                ldm_x4(ah[i], base + aoff + i * (16 * TPITCH) + kb);
                ldm_x4(al[i], base + TILE_B + aoff + i * (16 * TPITCH) + kb);
            }
            // ---- term-major: 3 passes of 16 INDEPENDENT MMAs ----
#pragma unroll
            for (int i = 0; i < 4; i++)
#pragma unroll
                for (int j = 0; j < 4; j++)
                    mma16816(acc[i][j], ah[i], bh[j]);
#pragma unroll
            for (int i = 0; i < 4; i++)
#pragma unroll
                for (int j = 0; j < 4; j++)
                    mma16816(acc[i][j], ah[i], bl[j]);
#pragma unroll
            for (int i = 0; i < 4; i++)
#pragma unroll
                for (int j = 0; j < 4; j++)
                    mma16816(acc[i][j], al[i], bh[j]);
        }
        if (++buf == 3) buf = 0;
    }

    float* Cz = Cf + (size_t)blockIdx.z * pstride;

    const int gid = lane >> 2;
    const int tig = lane & 3;
#pragma unroll
    for (int i = 0; i < 4; i++) {
#pragma unroll
        for (int j = 0; j < 4; j++) {
#pragma unroll
            for (int q = 0; q < 4; q++) {
                const int m  = m0 + wm * 64 + i * 16 + gid + (q >> 1) * 8;
                const int gn = n0 + wn * 32 + j * 8 + tig * 2 + (q & 1);
                if (gn >= Nreal) continue;
                float v = acc[i][j][q];
                if (EPI == 0) {
                    Cz[(size_t)m * ldc + gn] = v;
                } else if (EPI == 2) {
                    v += bias[gn];
                    v = (v > 20.f) ? v : log1pf(__expf(v));
                    Cz[(size_t)m * ldc + gn] = v;
                } else if (EPI == 3) {
                    const __nv_bfloat16 h = __float2bfloat16(v);
                    Ohi[(size_t)m * ldo + gn] = h;
                    Olo[(size_t)m * ldo + gn] = __float2bfloat16(v - __bfloat162float(h));
                } else { // EPI == 4
                    v += bias[gn];
                    const int b = m >> 11;
                    const int l = m & (L_SEQ - 1);
                    Cz[(size_t)b * ((size_t)DMODEL * L_SEQ) + (size_t)gn * L_SEQ + l] = v;
                }
            }
        }
    }
}

// ---------------------------------------------------------------------------
__global__ void __launch_bounds__(256)
xt_split_kernel(const float* __restrict__ x,
                __nv_bfloat16* __restrict__ hi, __nv_bfloat16* __restrict__ lo)
{
    __shared__ float t[32][33];
    const int b  = blockIdx.z;
    const int d0 = blockIdx.y * 32;
    const int l0 = blockIdx.x * 32;
    const int tx = threadIdx.x & 31;
    const int ty = threadIdx.x >> 5;
#pragma unroll
    for (int i = 0; i < 4; i++) {
        const int d = d0 + ty + i * 8;
        t[ty + i * 8][tx] = x[((size_t)b * DMODEL + d) * L_SEQ + l0 + tx];
    }
    __syncthreads();
#pragma unroll
    for (int i = 0; i < 4; i++) {
        const int l = l0 + ty + i * 8;
        const float v = t[tx][ty + i * 8];
        const size_t o = ((size_t)b * L_SEQ + l) * DMODEL + d0 + tx;
        const __nv_bfloat16 h = __float2bfloat16(v);
        hi[o] = h;
        lo[o] = __float2bfloat16(v - __bfloat162float(h));
    }
}

__global__ void __launch_bounds__(256)
split_kernel(const float* __restrict__ src, __nv_bfloat16* __restrict__ hi,
             __nv_bfloat16* __restrict__ lo, int n)
{
    const int i = blockIdx.x * 256 + threadIdx.x;
    if (i < n) {
        const float v = src[i];
        const __nv_bfloat16 h = __float2bfloat16(v);
        hi[i] = h;
        lo[i] = __float2bfloat16(v - __bfloat162float(h));
    }
}

__global__ void __launch_bounds__(256)
split2_kernel(const float* __restrict__ s1, __nv_bfloat16* __restrict__ h1,
              __nv_bfloat16* __restrict__ l1, int n1,
              const float* __restrict__ s2, __nv_bfloat16* __restrict__ h2,
              __nv_bfloat16* __restrict__ l2, int n2)
{
    const int i = blockIdx.x * 256 + threadIdx.x;
    if (i < n1) {
        const float v = s1[i];
        const __nv_bfloat16 h = __float2bfloat16(v);
        h1[i] = h;
        l1[i] = __float2bfloat16(v - __bfloat162float(h));
    } else if (i < n1 + n2) {
        const int j = i - n1;
        const float v = s2[j];
        const __nv_bfloat16 h = __float2bfloat16(v);
        h2[j] = h;
        l2[j] = __float2bfloat16(v - __bfloat162float(h));
    }
}

// ---------------------------------------------------------------------------
// x_proj split-K reduce: xdbl = sum of 4 partials; emit fp32 + bf16 split.
// ---------------------------------------------------------------------------
__global__ void __launch_bounds__(256)
xreduce_kernel()
{
    const int i = blockIdx.x * 256 + threadIdx.x;
    if (i >= MTOT * 96) return;
    const float v = g_xpart[0][i] + g_xpart[1][i] + g_xpart[2][i] + g_xpart[3][i];
    g_xdbl[i] = v;
    const __nv_bfloat16 h = __float2bfloat16(v);
    g_xd_hi[i] = h;
    g_xd_lo[i] = __float2bfloat16(v - __bfloat162float(h));
}

// ---------------------------------------------------------------------------
// Depthwise causal conv1d (k=4) + SiLU + bf16 split of result.
// ---------------------------------------------------------------------------
__global__ void __launch_bounds__(256)
conv_silu_kernel(const float* __restrict__ conv_w, const float* __restrict__ conv_b)
{
    const int idx = blockIdx.x * blockDim.x + threadIdx.x;
    const int d  = idx & (DI - 1);
    const int bl = idx >> 11;
    const int l  = bl & (L_SEQ - 1);

    float s = conv_b[d];
#pragma unroll
    for (int k = 0; k < 4; k++) {
        const int ll = l - 3 + k;
        if (ll >= 0)
            s += conv_w[d * 4 + k] * g_xz[(size_t)(bl - 3 + k) * 4096 + d];
    }
    const float sig = 1.f / (1.f + __expf(-s));
    const float y = s * sig;
    g_uact[(size_t)bl * DI + d] = y;
    const __nv_bfloat16 h = __float2bfloat16(y);
    g_ua_hi[(size_t)bl * DI + d] = h;
    g_ua_lo[(size_t)bl * DI + d] = __float2bfloat16(y - __bfloat162float(h));
}

// ---------------------------------------------------------------------------
// Selective scan, unrolled by 8 with batched prefetch.
// ---------------------------------------------------------------------------
__global__ void __launch_bounds__(128)
scan_kernel(const float* __restrict__ A_log, const float* __restrict__ Dp)
{
    const int b = blockIdx.y;
    const int g = threadIdx.x >> 4;
    const int n = threadIdx.x & 15;
    const int d = blockIdx.x * 8 + g;

    const float Aa = -__expf(A_log[d * DSTATE + n]);
    const float Dv = Dp[d];
    float h = 0.f;
    const int base = b * L_SEQ;

    for (int t0 = 0; t0 < L_SEQ; t0 += 8) {
        float dl[8], uu[8], Bn8[8], Cn8[8], zq[8];
#pragma unroll
        for (int q = 0; q < 8; q++) {
            const int bl = base + t0 + q;
            dl[q]  = g_delta[(size_t)bl * DI + d];
            uu[q]  = g_uact [(size_t)bl * DI + d];
            Bn8[q] = g_xdbl [(size_t)bl * 96 + 64 + n];
            Cn8[q] = g_xdbl [(size_t)bl * 96 + 80 + n];
            zq[q]  = g_xz   [(size_t)bl * 4096 + 2048 + d];
        }
#pragma unroll
        for (int q = 0; q < 8; q++) {
            h = __expf(dl[q] * Aa) * h + (dl[q] * uu[q]) * Bn8[q];
            float p = h * Cn8[q];
            p += __shfl_xor_sync(0xffffffffu, p, 8);
            p += __shfl_xor_sync(0xffffffffu, p, 4);
            p += __shfl_xor_sync(0xffffffffu, p, 2);
            p += __shfl_xor_sync(0xffffffffu, p, 1);
            if (n == 0) {
                const int bl = base + t0 + q;
                const float z   = zq[q];
                const float sig = 1.f / (1.f + __expf(-z));
                const float yv  = (p + uu[q] * Dv) * (z * sig);
                const __nv_bfloat16 hh = __float2bfloat16(yv);
                g_y_hi[(size_t)bl * DI + d] = hh;
                g_y_lo[(size_t)bl * DI + d] = __float2bfloat16(yv - __bfloat162float(hh));
            }
        }
    }
}

// ---------------------------------------------------------------------------
extern "C" void kernel_launch(void* const* d_in, const int* in_sizes, int n_in,
                              void* d_out, int out_size)
{
    const float* x       = (const float*)d_in[0];
    const float* in_w    = (const float*)d_in[1];
    const float* conv_w  = (const float*)d_in[2];
    const float* conv_b  = (const float*)d_in[3];
    const float* xproj_w = (const float*)d_in[4];
    const float* dt_w    = (const float*)d_in[5];
    const float* dt_b    = (const float*)d_in[6];
    const float* A_log   = (const float*)d_in[7];
    const float* Dp      = (const float*)d_in[8];
    const float* out_w   = (const float*)d_in[9];
    const float* proj_w  = (const float*)d_in[10];
    const float* proj_b  = (const float*)d_in[11];
    float* out = (float*)d_out;

    cudaFuncSetAttribute(tgemm_kernel<0>, cudaFuncAttributeMaxDynamicSharedMemorySize, SMEM_PIPE);
    cudaFuncSetAttribute(tgemm_kernel<2>, cudaFuncAttributeMaxDynamicSharedMemorySize, SMEM_PIPE);
    cudaFuncSetAttribute(tgemm_kernel<3>, cudaFuncAttributeMaxDynamicSharedMemorySize, SMEM_PIPE);
    cudaFuncSetAttribute(tgemm_kernel<4>, cudaFuncAttributeMaxDynamicSharedMemorySize, SMEM_PIPE);

    float *xz, *uact, *xdbl, *delta, *xpart;
    cudaGetSymbolAddress((void**)&xz,    g_xz);
    cudaGetSymbolAddress((void**)&uact,  g_uact);
    cudaGetSymbolAddress((void**)&xdbl,  g_xdbl);
    cudaGetSymbolAddress((void**)&delta, g_delta);
    cudaGetSymbolAddress((void**)&xpart, g_xpart);
    __nv_bfloat16 *xT_h, *xT_l, *ua_h, *ua_l, *xd_h, *xd_l, *y_h, *y_l, *t1_h, *t1_l;
    __nv_bfloat16 *inw_h, *inw_l, *xpw_h, *xpw_l, *dtw_h, *dtw_l, *ow_h, *ow_l, *pw_h, *pw_l;
    cudaGetSymbolAddress((void**)&xT_h, g_xT_hi);  cudaGetSymbolAddress((void**)&xT_l, g_xT_lo);
    cudaGetSymbolAddress((void**)&ua_h, g_ua_hi);  cudaGetSymbolAddress((void**)&ua_l, g_ua_lo);
    cudaGetSymbolAddress((void**)&xd_h, g_xd_hi);  cudaGetSymbolAddress((void**)&xd_l, g_xd_lo);
    cudaGetSymbolAddress((void**)&y_h,  g_y_hi);   cudaGetSymbolAddress((void**)&y_l,  g_y_lo);
    cudaGetSymbolAddress((void**)&t1_h, g_t1_hi);  cudaGetSymbolAddress((void**)&t1_l, g_t1_lo);
    cudaGetSymbolAddress((void**)&inw_h, g_inw_hi); cudaGetSymbolAddress((void**)&inw_l, g_inw_lo);
    cudaGetSymbolAddress((void**)&xpw_h, g_xpw_hi); cudaGetSymbolAddress((void**)&xpw_l, g_xpw_lo);
    cudaGetSymbolAddress((void**)&dtw_h, g_dtw_hi); cudaGetSymbolAddress((void**)&dtw_l, g_dtw_lo);
    cudaGetSymbolAddress((void**)&ow_h,  g_ow_hi);  cudaGetSymbolAddress((void**)&ow_l,  g_ow_lo);
    cudaGetSymbolAddress((void**)&pw_h,  g_pw_hi);  cudaGetSymbolAddress((void**)&pw_l,  g_pw_lo);

    // 0) x transpose + split
    xt_split_kernel<<<dim3(L_SEQ / 32, DMODEL / 32, NB), 256>>>(x, xT_h, xT_l);
    // 1) in_proj weight split
    split_kernel<<<(4096 * DMODEL + 255) / 256, 256>>>(in_w, inw_h, inw_l, 4096 * DMODEL);
    // 2) xproj + dt weight splits
    split2_kernel<<<(96 * DI + DI * DTRANK + 255) / 256, 256>>>(
        xproj_w, xpw_h, xpw_l, 96 * DI, dt_w, dtw_h, dtw_l, DI * DTRANK);

    // 3) in_proj GEMM  (launch index 3 -> profiled by ncu)
    tgemm_kernel<0><<<dim3(4096 / 128, MTOT / 128), 256, SMEM_PIPE>>>(
        xT_h, xT_l, DMODEL, inw_h, inw_l, DMODEL, DMODEL, 4096, 0,
        xz, 4096, nullptr, nullptr, nullptr, 0);

    // 4) out/proj weight splits
    split2_kernel<<<(DMODEL * DI + DMODEL * DMODEL + 255) / 256, 256>>>(
        out_w, ow_h, ow_l, DMODEL * DI, proj_w, pw_h, pw_l, DMODEL * DMODEL);

    // 5) conv + SiLU (+ split of uact)
    conv_silu_kernel<<<(MTOT * DI) / 256, 256>>>(conv_w, conv_b);

    // 6) x_proj, split-K=4: partials  (N=96, K=2048 -> 4 x 512)
    tgemm_kernel<0><<<dim3(1, MTOT / 128, 4), 256, SMEM_PIPE>>>(
        ua_h, ua_l, DI, xpw_h, xpw_l, DI, 512, 96, (size_t)MTOT * 96,
        xpart, 96, nullptr, nullptr, nullptr, 0);

    // 7) reduce partials -> xdbl fp32 + bf16 split
    xreduce_kernel<<<(MTOT * 96 + 255) / 256, 256>>>();

    // 8) dt_proj + softplus: delta  (N=2048, K=64)
    tgemm_kernel<2><<<dim3(DI / 128, MTOT / 128), 256, SMEM_PIPE>>>(
        xd_h, xd_l, 96, dtw_h, dtw_l, DTRANK, DTRANK, DI, 0,
        delta, DI, dt_b, nullptr, nullptr, 0);

    // 9) selective scan -> y (bf16 split)
    scan_kernel<<<dim3(DI / 8, NB), 128>>>(A_log, Dp);

    // 10) out_proj: t1 = y @ out_w^T  (N=1024, K=2048), split-only output
    tgemm_kernel<3><<<dim3(DMODEL / 128, MTOT / 128), 256, SMEM_PIPE>>>(
        y_h, y_l, DI, ow_h, ow_l, DI, DI, DMODEL, 0,
        nullptr, 0, nullptr, t1_h, t1_l, DMODEL);

    // 11) proj + bias, transposed store to (B, DMODEL, L)
    tgemm_kernel<4><<<dim3(DMODEL / 128, MTOT / 128), 256, SMEM_PIPE>>>(
        t1_h, t1_l, DMODEL, pw_h, pw_l, DMODEL, DMODEL, DMODEL, 0,
        out, 0, proj_b, nullptr, nullptr, 0);
}

// round 15
// speedup vs baseline: 1.7355x; 1.7355x over previous
#include <cuda_runtime.h>
#include <cuda_bf16.h>
#include <math.h>
#include <stdint.h>

// Problem constants
#define L_SEQ  2048
#define DMODEL 1024
#define DI     2048
#define NB     4
#define DSTATE 16
#define DTRANK 64
#define MTOT   (NB * L_SEQ)   // 8192

// ---------------------------------------------------------------------------
// Scratch (device globals)
// ---------------------------------------------------------------------------
__device__ float g_xz   [(size_t)MTOT * 4096];
__device__ float g_uact [(size_t)MTOT * DI];
__device__ float g_xdbl [(size_t)MTOT * 96];
__device__ float g_delta[(size_t)MTOT * DI];
__device__ float g_xpart[4][(size_t)MTOT * 96];   // x_proj split-K partials

__device__ __nv_bfloat16 g_xT_hi [(size_t)MTOT * DMODEL];
__device__ __nv_bfloat16 g_xT_lo [(size_t)MTOT * DMODEL];
__device__ __nv_bfloat16 g_ua_hi [(size_t)MTOT * DI];
__device__ __nv_bfloat16 g_ua_lo [(size_t)MTOT * DI];
__device__ __nv_bfloat16 g_xd_hi [(size_t)MTOT * 96];
__device__ __nv_bfloat16 g_xd_lo [(size_t)MTOT * 96];
__device__ __nv_bfloat16 g_y_hi  [(size_t)MTOT * DI];
__device__ __nv_bfloat16 g_y_lo  [(size_t)MTOT * DI];
__device__ __nv_bfloat16 g_t1_hi [(size_t)MTOT * DMODEL];
__device__ __nv_bfloat16 g_t1_lo [(size_t)MTOT * DMODEL];
__device__ __nv_bfloat16 g_inw_hi[(size_t)4096 * DMODEL];
__device__ __nv_bfloat16 g_inw_lo[(size_t)4096 * DMODEL];
__device__ __nv_bfloat16 g_xpw_hi[(size_t)96 * DI];
__device__ __nv_bfloat16 g_xpw_lo[(size_t)96 * DI];
__device__ __nv_bfloat16 g_dtw_hi[(size_t)DI * DTRANK];
__device__ __nv_bfloat16 g_dtw_lo[(size_t)DI * DTRANK];
__device__ __nv_bfloat16 g_ow_hi [(size_t)DMODEL * DI];
__device__ __nv_bfloat16 g_ow_lo [(size_t)DMODEL * DI];
__device__ __nv_bfloat16 g_pw_hi [(size_t)DMODEL * DMODEL];
__device__ __nv_bfloat16 g_pw_lo [(size_t)DMODEL * DMODEL];

// ---------------------------------------------------------------------------
// mma.sync helpers (plain sm_80+ PTX)
// ---------------------------------------------------------------------------
__device__ __forceinline__ uint32_t smem_u32_of(const void* p) {
    uint32_t a;
    asm("{ .reg .u64 t; cvta.to.shared.u64 t, %1; cvt.u32.u64 %0, t; }"
        : "=r"(a) : "l"(p));
    return a;
}
__device__ __forceinline__ void ldm_x4(uint32_t* r, uint32_t addr) {
    asm volatile("ldmatrix.sync.aligned.m8n8.x4.shared.b16 {%0,%1,%2,%3}, [%4];"
                 : "=r"(r[0]), "=r"(r[1]), "=r"(r[2]), "=r"(r[3]) : "r"(addr));
}
__device__ __forceinline__ void ldm_x2(uint32_t* r, uint32_t addr) {
    asm volatile("ldmatrix.sync.aligned.m8n8.x2.shared.b16 {%0,%1}, [%2];"
                 : "=r"(r[0]), "=r"(r[1]) : "r"(addr));
}
__device__ __forceinline__ void mma16816(float* c, const uint32_t* a, const uint32_t* b) {
    asm volatile(
        "mma.sync.aligned.m16n8k16.row.col.f32.bf16.bf16.f32 "
        "{%0,%1,%2,%3}, {%4,%5,%6,%7}, {%8,%9}, {%0,%1,%2,%3};"
        : "+f"(c[0]), "+f"(c[1]), "+f"(c[2]), "+f"(c[3])
        : "r"(a[0]), "r"(a[1]), "r"(a[2]), "r"(a[3]), "r"(b[0]), "r"(b[1]));
}
__device__ __forceinline__ void cpa16(uint32_t dst, const void* src, int szbytes) {
    asm volatile("cp.async.cg.shared.global [%0], [%1], 16, %2;"
                 :: "r"(dst), "l"(src), "r"(szbytes));
}

#define TPITCH   80
#define TILE_B   10240
#define BUF_B    40960
#define SMEM_PIPE (2 * BUF_B)    // double buffer = 81920 B -> 2 CTAs/SM

// ---------------------------------------------------------------------------
// Tensor-core GEMM (bf16 2-term split, 3 MMAs, term-major scheduling).
// CTA 128x128, BK=32, 256 threads (8 warps of 64x32), 2 CTAs/SM.
// Mainloop identical to the R10 kernel measured at 2115 us.
// Split-K aware: blockIdx.z selects K-slice of length ksl.
// EPI 0: fp32   EPI 2: softplus(v+bias) fp32   EPI 3: bf16-split only
// EPI 4: (v+bias) transposed store
// ---------------------------------------------------------------------------
template <int EPI>
__global__ void __launch_bounds__(256, 2)
tgemm_kernel(const __nv_bfloat16* __restrict__ Ahi, const __nv_bfloat16* __restrict__ Alo, int lda,
             const __nv_bfloat16* __restrict__ Bhi, const __nv_bfloat16* __restrict__ Blo, int ldb,
             int ksl, int Nreal, size_t pstride,
             float* __restrict__ Cf, int ldc, const float* __restrict__ bias,
             __nv_bfloat16* __restrict__ Ohi, __nv_bfloat16* __restrict__ Olo, int ldo)
{
    extern __shared__ __align__(128) char smem[];
    const int tid  = threadIdx.x;
    const int lane = tid & 31;
    const int wm   = (tid >> 5) & 1;
    const int wn   = tid >> 6;
    const int n0   = blockIdx.x * 128;
    const int m0   = blockIdx.y * 128;
    const int kbase = blockIdx.z * ksl;
    const uint32_t sb = smem_u32_of(smem);

    float acc[4][4][4];
#pragma unroll
    for (int i = 0; i < 4; i++)
#pragma unroll
        for (int j = 0; j < 4; j++)
#pragma unroll
            for (int q = 0; q < 4; q++) acc[i][j][q] = 0.f;

    const int r0  = (tid * 2) >> 2;
    const int s0  = (tid * 2) & 3;
    const int r1  = (tid * 2 + 1) >> 2;
    const int s1  = (tid * 2 + 1) & 3;

    auto issue = [&](int buf, int c) {
        const int k0 = kbase + (c << 5);
        const uint32_t base = sb + buf * BUF_B;
        {
            const uint32_t d = base + r0 * TPITCH + s0 * 16;
            cpa16(d,            Ahi + (size_t)(m0 + r0) * lda + k0 + s0 * 8, 16);
            cpa16(d + TILE_B,   Alo + (size_t)(m0 + r0) * lda + k0 + s0 * 8, 16);
            const bool ok = (n0 + r0) < Nreal;
            const int  nr = ok ? (n0 + r0) : 0;
            cpa16(d + 2 * TILE_B, Bhi + (size_t)nr * ldb + k0 + s0 * 8, ok ? 16 : 0);
            cpa16(d + 3 * TILE_B, Blo + (size_t)nr * ldb + k0 + s0 * 8, ok ? 16 : 0);
        }
        {
            const uint32_t d = base + r1 * TPITCH + s1 * 16;
            cpa16(d,            Ahi + (size_t)(m0 + r1) * lda + k0 + s1 * 8, 16);
            cpa16(d + TILE_B,   Alo + (size_t)(m0 + r1) * lda + k0 + s1 * 8, 16);
            const bool ok = (n0 + r1) < Nreal;
            const int  nr = ok ? (n0 + r1) : 0;
            cpa16(d + 2 * TILE_B, Bhi + (size_t)nr * ldb + k0 + s1 * 8, ok ? 16 : 0);
            cpa16(d + 3 * TILE_B, Blo + (size_t)nr * ldb + k0 + s1 * 8, ok ? 16 : 0);
        }
        asm volatile("cp.async.commit_group;");
    };

    const uint32_t aoff =
        (uint32_t)((wm * 64 + (lane & 7) + 8 * ((lane >> 3) & 1)) * TPITCH + (8 * (lane >> 4)) * 2);
    const uint32_t boff =
        (uint32_t)((wn * 32 + (lane & 7)) * TPITCH + (8 * ((lane >> 3) & 1)) * 2);

    const int nchunks = ksl >> 5;
    issue(0, 0);

    for (int c = 0; c < nchunks; c++) {
        asm volatile("cp.async.wait_group 0;");
        __syncthreads();
        if (c + 1 < nchunks) issue((c + 1) & 1, c + 1);

        const uint32_t base = sb + (c & 1) * BUF_B;
#pragma unroll
        for (int ks = 0; ks < 2; ks++) {
            const uint32_t kb = ks * 32;
            // ---- load ALL fragments for this k-step first ----
            uint32_t bh[4][2], bl[4][2], ah[4][4], al[4][4];
#pragma unroll
            for (int j = 0; j < 4; j++) {
                ldm_x2(bh[j], base + 2 * TILE_B + boff + j * (8 * TPITCH) + kb);
                ldm_x2(bl[j], base + 3 * TILE_B + boff + j * (8 * TPITCH) + kb);
            }
#pragma unroll
            for (int i = 0; i < 4; i++) {
                ldm_x4(ah[i], base + aoff + i * (16 * TPITCH) + kb);
                ldm_x4(al[i], base + TILE_B + aoff + i * (16 * TPITCH) + kb);
            }
            // ---- term-major: 3 passes of 16 INDEPENDENT MMAs ----
#pragma unroll
            for (int i = 0; i < 4; i++)
#pragma unroll
                for (int j = 0; j < 4; j++)
                    mma16816(acc[i][j], ah[i], bh[j]);
#pragma unroll
            for (int i = 0; i < 4; i++)
#pragma unroll
                for (int j = 0; j < 4; j++)
                    mma16816(acc[i][j], ah[i], bl[j]);
#pragma unroll
            for (int i = 0; i < 4; i++)
#pragma unroll
                for (int j = 0; j < 4; j++)
                    mma16816(acc[i][j], al[i], bh[j]);
        }
        __syncthreads();
    }

    float* Cz = Cf + (size_t)blockIdx.z * pstride;

    const int gid = lane >> 2;
    const int tig = lane & 3;
#pragma unroll
    for (int i = 0; i < 4; i++) {
#pragma unroll
        for (int j = 0; j < 4; j++) {
#pragma unroll
            for (int q = 0; q < 4; q++) {
                const int m  = m0 + wm * 64 + i * 16 + gid + (q >> 1) * 8;
                const int gn = n0 + wn * 32 + j * 8 + tig * 2 + (q & 1);
                if (gn >= Nreal) continue;
                float v = acc[i][j][q];
                if (EPI == 0) {
                    Cz[(size_t)m * ldc + gn] = v;
                } else if (EPI == 2) {
                    v += bias[gn];
                    v = (v > 20.f) ? v : log1pf(__expf(v));
                    Cz[(size_t)m * ldc + gn] = v;
                } else if (EPI == 3) {
                    const __nv_bfloat16 h = __float2bfloat16(v);
                    Ohi[(size_t)m * ldo + gn] = h;
                    Olo[(size_t)m * ldo + gn] = __float2bfloat16(v - __bfloat162float(h));
                } else { // EPI == 4
                    v += bias[gn];
                    const int b = m >> 11;
                    const int l = m & (L_SEQ - 1);
                    Cz[(size_t)b * ((size_t)DMODEL * L_SEQ) + (size_t)gn * L_SEQ + l] = v;
                }
            }
        }
    }
}

// ---------------------------------------------------------------------------
__global__ void __launch_bounds__(256)
xt_split_kernel(const float* __restrict__ x,
                __nv_bfloat16* __restrict__ hi, __nv_bfloat16* __restrict__ lo)
{
    __shared__ float t[32][33];
    const int b  = blockIdx.z;
    const int d0 = blockIdx.y * 32;
    const int l0 = blockIdx.x * 32;
    const int tx = threadIdx.x & 31;
    const int ty = threadIdx.x >> 5;
#pragma unroll
    for (int i = 0; i < 4; i++) {
        const int d = d0 + ty + i * 8;
        t[ty + i * 8][tx] = x[((size_t)b * DMODEL + d) * L_SEQ + l0 + tx];
    }
    __syncthreads();
#pragma unroll
    for (int i = 0; i < 4; i++) {
        const int l = l0 + ty + i * 8;
        const float v = t[tx][ty + i * 8];
        const size_t o = ((size_t)b * L_SEQ + l) * DMODEL + d0 + tx;
        const __nv_bfloat16 h = __float2bfloat16(v);
        hi[o] = h;
        lo[o] = __float2bfloat16(v - __bfloat162float(h));
    }
}

__global__ void __launch_bounds__(256)
split_kernel(const float* __restrict__ src, __nv_bfloat16* __restrict__ hi,
             __nv_bfloat16* __restrict__ lo, int n)
{
    const int i = blockIdx.x * 256 + threadIdx.x;
    if (i < n) {
        const float v = src[i];
        const __nv_bfloat16 h = __float2bfloat16(v);
        hi[i] = h;
        lo[i] = __float2bfloat16(v - __bfloat162float(h));
    }
}

__global__ void __launch_bounds__(256)
split2_kernel(const float* __restrict__ s1, __nv_bfloat16* __restrict__ h1,
              __nv_bfloat16* __restrict__ l1, int n1,
              const float* __restrict__ s2, __nv_bfloat16* __restrict__ h2,
              __nv_bfloat16* __restrict__ l2, int n2)
{
    const int i = blockIdx.x * 256 + threadIdx.x;
    if (i < n1) {
        const float v = s1[i];
        const __nv_bfloat16 h = __float2bfloat16(v);
        h1[i] = h;
        l1[i] = __float2bfloat16(v - __bfloat162float(h));
    } else if (i < n1 + n2) {
        const int j = i - n1;
        const float v = s2[j];
        const __nv_bfloat16 h = __float2bfloat16(v);
        h2[j] = h;
        l2[j] = __float2bfloat16(v - __bfloat162float(h));
    }
}

// ---------------------------------------------------------------------------
// x_proj split-K reduce: xdbl = sum of 4 partials; emit fp32 + bf16 split.
// ---------------------------------------------------------------------------
__global__ void __launch_bounds__(256)
xreduce_kernel()
{
    const int i = blockIdx.x * 256 + threadIdx.x;
    if (i >= MTOT * 96) return;
    const float v = g_xpart[0][i] + g_xpart[1][i] + g_xpart[2][i] + g_xpart[3][i];
    g_xdbl[i] = v;
    const __nv_bfloat16 h = __float2bfloat16(v);
    g_xd_hi[i] = h;
    g_xd_lo[i] = __float2bfloat16(v - __bfloat162float(h));
}

// ---------------------------------------------------------------------------
// Depthwise causal conv1d (k=4) + SiLU + bf16 split of result.
// ---------------------------------------------------------------------------
__global__ void __launch_bounds__(256)
conv_silu_kernel(const float* __restrict__ conv_w, const float* __restrict__ conv_b)
{
    const int idx = blockIdx.x * blockDim.x + threadIdx.x;
    const int d  = idx & (DI - 1);
    const int bl = idx >> 11;
    const int l  = bl & (L_SEQ - 1);

    float s = conv_b[d];
#pragma unroll
    for (int k = 0; k < 4; k++) {
        const int ll = l - 3 + k;
        if (ll >= 0)
            s += conv_w[d * 4 + k] * g_xz[(size_t)(bl - 3 + k) * 4096 + d];
    }
    const float sig = 1.f / (1.f + __expf(-s));
    const float y = s * sig;
    g_uact[(size_t)bl * DI + d] = y;
    const __nv_bfloat16 h = __float2bfloat16(y);
    g_ua_hi[(size_t)bl * DI + d] = h;
    g_ua_lo[(size_t)bl * DI + d] = __float2bfloat16(y - __bfloat162float(h));
}

// ---------------------------------------------------------------------------
// Selective scan, unrolled by 8 with batched prefetch.
// ---------------------------------------------------------------------------
__global__ void __launch_bounds__(128)
scan_kernel(const float* __restrict__ A_log, const float* __restrict__ Dp)
{
    const int b = blockIdx.y;
    const int g = threadIdx.x >> 4;
    const int n = threadIdx.x & 15;
    const int d = blockIdx.x * 8 + g;

    const float Aa = -__expf(A_log[d * DSTATE + n]);
    const float Dv = Dp[d];
    float h = 0.f;
    const int base = b * L_SEQ;

    for (int t0 = 0; t0 < L_SEQ; t0 += 8) {
        float dl[8], uu[8], Bn8[8], Cn8[8], zq[8];
#pragma unroll
        for (int q = 0; q < 8; q++) {
            const int bl = base + t0 + q;
            dl[q]  = g_delta[(size_t)bl * DI + d];
            uu[q]  = g_uact [(size_t)bl * DI + d];
            Bn8[q] = g_xdbl [(size_t)bl * 96 + 64 + n];
            Cn8[q] = g_xdbl [(size_t)bl * 96 + 80 + n];
            zq[q]  = g_xz   [(size_t)bl * 4096 + 2048 + d];
        }
#pragma unroll
        for (int q = 0; q < 8; q++) {
            h = __expf(dl[q] * Aa) * h + (dl[q] * uu[q]) * Bn8[q];
            float p = h * Cn8[q];
            p += __shfl_xor_sync(0xffffffffu, p, 8);
            p += __shfl_xor_sync(0xffffffffu, p, 4);
            p += __shfl_xor_sync(0xffffffffu, p, 2);
            p += __shfl_xor_sync(0xffffffffu, p, 1);
            if (n == 0) {
                const int bl = base + t0 + q;
                const float z   = zq[q];
                const float sig = 1.f / (1.f + __expf(-z));
                const float yv  = (p + uu[q] * Dv) * (z * sig);
                const __nv_bfloat16 hh = __float2bfloat16(yv);
                g_y_hi[(size_t)bl * DI + d] = hh;
                g_y_lo[(size_t)bl * DI + d] = __float2bfloat16(yv - __bfloat162float(hh));
            }
        }
    }
}

// ---------------------------------------------------------------------------
extern "C" void kernel_launch(void* const* d_in, const int* in_sizes, int n_in,
                              void* d_out, int out_size)
{
    const float* x       = (const float*)d_in[0];
    const float* in_w    = (const float*)d_in[1];
    const float* conv_w  = (const float*)d_in[2];
    const float* conv_b  = (const float*)d_in[3];
    const float* xproj_w = (const float*)d_in[4];
    const float* dt_w    = (const float*)d_in[5];
    const float* dt_b    = (const float*)d_in[6];
    const float* A_log   = (const float*)d_in[7];
    const float* Dp      = (const float*)d_in[8];
    const float* out_w   = (const float*)d_in[9];
    const float* proj_w  = (const float*)d_in[10];
    const float* proj_b  = (const float*)d_in[11];
    float* out = (float*)d_out;

    cudaFuncSetAttribute(tgemm_kernel<0>, cudaFuncAttributeMaxDynamicSharedMemorySize, SMEM_PIPE);
    cudaFuncSetAttribute(tgemm_kernel<2>, cudaFuncAttributeMaxDynamicSharedMemorySize, SMEM_PIPE);
    cudaFuncSetAttribute(tgemm_kernel<3>, cudaFuncAttributeMaxDynamicSharedMemorySize, SMEM_PIPE);
    cudaFuncSetAttribute(tgemm_kernel<4>, cudaFuncAttributeMaxDynamicSharedMemorySize, SMEM_PIPE);

    float *xz, *uact, *xdbl, *delta, *xpart;
    cudaGetSymbolAddress((void**)&xz,    g_xz);
    cudaGetSymbolAddress((void**)&uact,  g_uact);
    cudaGetSymbolAddress((void**)&xdbl,  g_xdbl);
    cudaGetSymbolAddress((void**)&delta, g_delta);
    cudaGetSymbolAddress((void**)&xpart, g_xpart);
    __nv_bfloat16 *xT_h, *xT_l, *ua_h, *ua_l, *xd_h, *xd_l, *y_h, *y_l, *t1_h, *t1_l;
    __nv_bfloat16 *inw_h, *inw_l, *xpw_h, *xpw_l, *dtw_h, *dtw_l, *ow_h, *ow_l, *pw_h, *pw_l;
    cudaGetSymbolAddress((void**)&xT_h, g_xT_hi);  cudaGetSymbolAddress((void**)&xT_l, g_xT_lo);
    cudaGetSymbolAddress((void**)&ua_h, g_ua_hi);  cudaGetSymbolAddress((void**)&ua_l, g_ua_lo);
    cudaGetSymbolAddress((void**)&xd_h, g_xd_hi);  cudaGetSymbolAddress((void**)&xd_l, g_xd_lo);
    cudaGetSymbolAddress((void**)&y_h,  g_y_hi);   cudaGetSymbolAddress((void**)&y_l,  g_y_lo);
    cudaGetSymbolAddress((void**)&t1_h, g_t1_hi);  cudaGetSymbolAddress((void**)&t1_l, g_t1_lo);
    cudaGetSymbolAddress((void**)&inw_h, g_inw_hi); cudaGetSymbolAddress((void**)&inw_l, g_inw_lo);
    cudaGetSymbolAddress((void**)&xpw_h, g_xpw_hi); cudaGetSymbolAddress((void**)&xpw_l, g_xpw_lo);
    cudaGetSymbolAddress((void**)&dtw_h, g_dtw_hi); cudaGetSymbolAddress((void**)&dtw_l, g_dtw_lo);
    cudaGetSymbolAddress((void**)&ow_h,  g_ow_hi);  cudaGetSymbolAddress((void**)&ow_l,  g_ow_lo);
    cudaGetSymbolAddress((void**)&pw_h,  g_pw_hi);  cudaGetSymbolAddress((void**)&pw_l,  g_pw_lo);

    // 0) x transpose + split
    xt_split_kernel<<<dim3(L_SEQ / 32, DMODEL / 32, NB), 256>>>(x, xT_h, xT_l);
    // 1) in_proj weight split
    split_kernel<<<(4096 * DMODEL + 255) / 256, 256>>>(in_w, inw_h, inw_l, 4096 * DMODEL);
    // 2) xproj + dt weight splits
    split2_kernel<<<(96 * DI + DI * DTRANK + 255) / 256, 256>>>(
        xproj_w, xpw_h, xpw_l, 96 * DI, dt_w, dtw_h, dtw_l, DI * DTRANK);

    // 3) in_proj GEMM  (launch index 3 -> profiled by ncu)
    tgemm_kernel<0><<<dim3(4096 / 128, MTOT / 128), 256, SMEM_PIPE>>>(
        xT_h, xT_l, DMODEL, inw_h, inw_l, DMODEL, DMODEL, 4096, 0,
        xz, 4096, nullptr, nullptr, nullptr, 0);

    // 4) out/proj weight splits
    split2_kernel<<<(DMODEL * DI + DMODEL * DMODEL + 255) / 256, 256>>>(
        out_w, ow_h, ow_l, DMODEL * DI, proj_w, pw_h, pw_l, DMODEL * DMODEL);

    // 5) conv + SiLU (+ split of uact)
    conv_silu_kernel<<<(MTOT * DI) / 256, 256>>>(conv_w, conv_b);

    // 6) x_proj, split-K=4: partials  (N=96, K=2048 -> 4 x 512)
    tgemm_kernel<0><<<dim3(1, MTOT / 128, 4), 256, SMEM_PIPE>>>(
        ua_h, ua_l, DI, xpw_h, xpw_l, DI, 512, 96, (size_t)MTOT * 96,
        xpart, 96, nullptr, nullptr, nullptr, 0);

    // 7) reduce partials -> xdbl fp32 + bf16 split
    xreduce_kernel<<<(MTOT * 96 + 255) / 256, 256>>>();

    // 8) dt_proj + softplus: delta  (N=2048, K=64)
    tgemm_kernel<2><<<dim3(DI / 128, MTOT / 128), 256, SMEM_PIPE>>>(
        xd_h, xd_l, 96, dtw_h, dtw_l, DTRANK, DTRANK, DI, 0,
        delta, DI, dt_b, nullptr, nullptr, 0);

    // 9) selective scan -> y (bf16 split)
    scan_kernel<<<dim3(DI / 8, NB), 128>>>(A_log, Dp);

    // 10) out_proj: t1 = y @ out_w^T  (N=1024, K=2048), split-only output
    tgemm_kernel<3><<<dim3(DMODEL / 128, MTOT / 128), 256, SMEM_PIPE>>>(
        y_h, y_l, DI, ow_h, ow_l, DI, DI, DMODEL, 0,
        nullptr, 0, nullptr, t1_h, t1_l, DMODEL);

    // 11) proj + bias, transposed store to (B, DMODEL, L)
    tgemm_kernel<4><<<dim3(DMODEL / 128, MTOT / 128), 256, SMEM_PIPE>>>(
        t1_h, t1_l, DMODEL, pw_h, pw_l, DMODEL, DMODEL, DMODEL, 0,
        out, 0, proj_b, nullptr, nullptr, 0);
}